// round 2
// baseline (speedup 1.0000x reference)
#include <cuda_runtime.h>
#include <cuda_bf16.h>

// Problem constants
#define U 64
#define M 8192
#define D 64
#define NEG_INF (-1e9f)

// d_out layout (tuple flatten order): outputs[U*D] | weights[U*M] | memories[U*M*D]
#define OUT_OUTPUTS_OFF 0
#define OUT_WEIGHTS_OFF (U * D)
#define OUT_MEMCOPY_OFF (U * D + U * M)

// Scratch (no cudaMalloc allowed)
__device__ float g_exp[U * M];   // exp(masked score / tmpr), pre-normalization
__device__ float g_sum[U];       // per-unit sum of exps

// ---------------------------------------------------------------------------
// Kernel Z: zero g_sum and the outputs region of d_out (d_out is poisoned).
// ---------------------------------------------------------------------------
__global__ void zero_kernel(float* __restrict__ out) {
    int i = blockIdx.x * blockDim.x + threadIdx.x;
    if (i < U * D) out[OUT_OUTPUTS_OFF + i] = 0.0f;
    if (i < U) g_sum[i] = 0.0f;
}

// ---------------------------------------------------------------------------
// Kernel A: scores -> exp -> scratch + per-unit sum.
// Block = 256 threads, covers 16 consecutive slots of one unit.
// 16 lanes per slot: each lane loads a float4 of the slot's 64-d row,
// partial dot with the unit query, shfl-reduce within the 16-lane group.
// Grid = U * (M/16) = 32768 blocks.
// ---------------------------------------------------------------------------
__global__ __launch_bounds__(256) void score_kernel(
    const float* __restrict__ attention,       // [U, D]
    const float* __restrict__ attentions,      // [U, M, D]
    const float* __restrict__ tmpr,            // [U, 1]
    const int* __restrict__ mask)              // [U, M] (bool stored as int32)
{
    const int b = blockIdx.x;
    const int u = b >> 9;                 // / (M/16 = 512)
    const int mbase = (b & 511) << 4;     // *16

    const int tid  = threadIdx.x;
    const int lane = tid & 31;
    const int warp = tid >> 5;
    const int grp  = lane >> 4;           // 0 or 1: which slot in this warp
    const int l16  = lane & 15;           // lane within the 16-lane group

    const int slot = mbase + warp * 2 + grp;

    // Query fragment for this lane (broadcast across slots of the unit)
    const float4 a4 = *reinterpret_cast<const float4*>(attention + u * D + l16 * 4);
    const float4 v4 = *reinterpret_cast<const float4*>(
        attentions + ((size_t)u * M + slot) * D + l16 * 4);

    float p = a4.x * v4.x + a4.y * v4.y + a4.z * v4.z + a4.w * v4.w;

    // Reduce across the 16-lane group
    #pragma unroll
    for (int off = 8; off >= 1; off >>= 1)
        p += __shfl_down_sync(0xffffffffu, p, off, 16);

    __shared__ float bsum;
    if (tid == 0) bsum = 0.0f;
    __syncthreads();

    if (l16 == 0) {
        float s = mask[u * M + slot] ? NEG_INF : p;
        s /= tmpr[u];
        float e = __expf(s);              // masked -> exp(-1.25e8) == 0 exactly
        g_exp[u * M + slot] = e;
        atomicAdd(&bsum, e);
    }
    __syncthreads();
    if (tid == 0) atomicAdd(&g_sum[u], bsum);
}

// ---------------------------------------------------------------------------
// Kernel B: normalize -> weights out; stream memories once -> weighted sum
// (shared reduce + atomics into outputs) AND verbatim copy to d_out.
// Block = 256 threads, covers 128 consecutive slots of one unit
// (16 slots per iteration x 8 iterations). Grid = U * (M/128) = 4096 blocks.
// ---------------------------------------------------------------------------
__global__ __launch_bounds__(256) void output_kernel(
    const float* __restrict__ memories,   // [U, M, D]
    float* __restrict__ out)
{
    const int b = blockIdx.x;
    const int u = b >> 6;                 // / (M/128 = 64)
    const int mbase = (b & 63) << 7;      // *128

    const int tid = threadIdx.x;
    const int g   = tid >> 4;             // slot-group 0..15
    const int l16 = tid & 15;             // float4 index within 64-d row

    const float inv = 1.0f / g_sum[u];

    const float4* __restrict__ memv =
        reinterpret_cast<const float4*>(memories) + ((size_t)u * M) * (D / 4);
    float4* __restrict__ copyv =
        reinterpret_cast<float4*>(out + OUT_MEMCOPY_OFF) + ((size_t)u * M) * (D / 4);
    float* __restrict__ wout = out + OUT_WEIGHTS_OFF + u * M;

    float4 acc = make_float4(0.f, 0.f, 0.f, 0.f);

    #pragma unroll
    for (int i = 0; i < 8; i++) {
        const int slot = mbase + i * 16 + g;
        const float w = g_exp[u * M + slot] * inv;
        const float4 v = memv[(size_t)slot * (D / 4) + l16];
        copyv[(size_t)slot * (D / 4) + l16] = v;  // verbatim memories copy
        acc.x += w * v.x; acc.y += w * v.y;
        acc.z += w * v.z; acc.w += w * v.w;
        if (l16 == 0) wout[slot] = w;             // normalized weights
    }

    // Reduce acc across the 16 slot-groups (per dim-lane l16)
    __shared__ float4 sh[256];
    sh[tid] = acc;
    __syncthreads();
    #pragma unroll
    for (int stride = 128; stride >= 16; stride >>= 1) {
        if (tid < stride) {
            float4 o = sh[tid + stride];
            sh[tid].x += o.x; sh[tid].y += o.y;
            sh[tid].z += o.z; sh[tid].w += o.w;
        }
        __syncthreads();
    }
    if (tid < 16) {
        float4 r = sh[tid];
        float* dst = out + OUT_OUTPUTS_OFF + u * D + tid * 4;
        atomicAdd(dst + 0, r.x);
        atomicAdd(dst + 1, r.y);
        atomicAdd(dst + 2, r.z);
        atomicAdd(dst + 3, r.w);
    }
}

// ---------------------------------------------------------------------------
extern "C" void kernel_launch(void* const* d_in, const int* in_sizes, int n_in,
                              void* d_out, int out_size) {
    const float* attention   = (const float*)d_in[0];  // [U, D]
    const float* attentions  = (const float*)d_in[1];  // [U, M, D]
    const float* memories    = (const float*)d_in[2];  // [U, M, D]
    const float* tmpr        = (const float*)d_in[3];  // [U, 1]
    const int*   mask        = (const int*)d_in[4];    // [U, M] bool as int32

    float* out = (float*)d_out;

    zero_kernel<<<(U * D + 255) / 256, 256>>>(out);
    score_kernel<<<U * (M / 16), 256>>>(attention, attentions, tmpr, mask);
    output_kernel<<<U * (M / 128), 256>>>(memories, out);
}

// round 3
// speedup vs baseline: 1.2557x; 1.2557x over previous
#include <cuda_runtime.h>
#include <cuda_bf16.h>

// Problem constants
#define U 64
#define M 8192
#define D 64
#define NEG_INF (-1e9f)

// d_out layout (tuple flatten order): outputs[U*D] | weights[U*M] | memories[U*M*D]
#define OUT_OUTPUTS_OFF 0
#define OUT_WEIGHTS_OFF (U * D)
#define OUT_MEMCOPY_OFF (U * D + U * M)

// Scratch (no cudaMalloc allowed)
__device__ float g_exp[U * M];   // exp(masked score / tmpr), pre-normalization
__device__ float g_sum[U];       // per-unit sum of exps

// ---------------------------------------------------------------------------
// Kernel A: scores -> exp -> scratch.  PURE STREAMING: no smem, no barriers,
// no atomics.  Block = 256 threads covers 16 consecutive slots of one unit;
// 16 lanes per slot do the 64-d dot via float4 + shfl.  Grid = U*(M/16).
// ---------------------------------------------------------------------------
__global__ __launch_bounds__(256) void score_kernel(
    const float* __restrict__ attention,       // [U, D]
    const float* __restrict__ attentions,      // [U, M, D]
    const float* __restrict__ tmpr,            // [U, 1]
    const int* __restrict__ mask)              // [U, M] (bool stored as int32)
{
    const int b = blockIdx.x;
    const int u = b >> 9;                 // / (M/16 = 512)
    const int mbase = (b & 511) << 4;     // *16

    const int tid  = threadIdx.x;
    const int lane = tid & 31;
    const int warp = tid >> 5;
    const int grp  = lane >> 4;           // 0 or 1: which slot in this warp
    const int l16  = lane & 15;           // lane within the 16-lane group

    const int slot = mbase + warp * 2 + grp;

    const float4 a4 = *reinterpret_cast<const float4*>(attention + u * D + l16 * 4);
    const float4 v4 = __ldcs(reinterpret_cast<const float4*>(
        attentions + ((size_t)u * M + slot) * D) + l16);

    float p = a4.x * v4.x + a4.y * v4.y + a4.z * v4.z + a4.w * v4.w;

    #pragma unroll
    for (int off = 8; off >= 1; off >>= 1)
        p += __shfl_down_sync(0xffffffffu, p, off, 16);

    if (l16 == 0) {
        float s = mask[u * M + slot] ? NEG_INF : p;
        s /= tmpr[u];
        g_exp[u * M + slot] = __expf(s);  // masked -> underflows to exactly 0
    }
}

// ---------------------------------------------------------------------------
// Kernel B: per-unit sum of exps (g_exp is L2-resident) + zero the outputs
// region of d_out (it is poisoned before each timed replay).
// Grid = U blocks, 256 threads.
// ---------------------------------------------------------------------------
__global__ __launch_bounds__(256) void sum_kernel(float* __restrict__ out) {
    const int u = blockIdx.x;
    const int tid = threadIdx.x;

    float s = 0.0f;
    const float4* ev = reinterpret_cast<const float4*>(g_exp + u * M);
    #pragma unroll
    for (int i = 0; i < M / 4 / 256; i++) {     // 8 iterations
        float4 e = ev[i * 256 + tid];
        s += (e.x + e.y) + (e.z + e.w);
    }

    __shared__ float sh[256];
    sh[tid] = s;
    __syncthreads();
    #pragma unroll
    for (int stride = 128; stride >= 32; stride >>= 1) {
        if (tid < stride) sh[tid] += sh[tid + stride];
        __syncthreads();
    }
    if (tid < 32) {
        float v = sh[tid];
        #pragma unroll
        for (int off = 16; off >= 1; off >>= 1)
            v += __shfl_down_sync(0xffffffffu, v, off);
        if (tid == 0) g_sum[u] = v;
    }

    if (tid < D) out[OUT_OUTPUTS_OFF + u * D + tid] = 0.0f;
}

// ---------------------------------------------------------------------------
// Kernel C: normalize -> weights out; stream memories once -> weighted sum
// (shared reduce + atomics into outputs) AND verbatim copy to d_out.
// Block = 256 threads covers 128 consecutive slots of one unit.
// Grid = U * (M/128) = 4096 blocks.
// ---------------------------------------------------------------------------
__global__ __launch_bounds__(256) void output_kernel(
    const float* __restrict__ memories,   // [U, M, D]
    float* __restrict__ out)
{
    const int b = blockIdx.x;
    const int u = b >> 6;                 // / (M/128 = 64)
    const int mbase = (b & 63) << 7;      // *128

    const int tid = threadIdx.x;
    const int g   = tid >> 4;             // slot-group 0..15
    const int l16 = tid & 15;             // float4 index within 64-d row

    const float inv = 1.0f / g_sum[u];

    const float4* __restrict__ memv =
        reinterpret_cast<const float4*>(memories) + ((size_t)u * M) * (D / 4);
    float4* __restrict__ copyv =
        reinterpret_cast<float4*>(out + OUT_MEMCOPY_OFF) + ((size_t)u * M) * (D / 4);
    float* __restrict__ wout = out + OUT_WEIGHTS_OFF + u * M;

    float4 acc = make_float4(0.f, 0.f, 0.f, 0.f);

    #pragma unroll
    for (int i = 0; i < 8; i++) {
        const int slot = mbase + i * 16 + g;
        const float w = g_exp[u * M + slot] * inv;
        const float4 v = __ldcs(memv + (size_t)slot * (D / 4) + l16);
        __stcs(copyv + (size_t)slot * (D / 4) + l16, v);  // verbatim copy
        acc.x += w * v.x; acc.y += w * v.y;
        acc.z += w * v.z; acc.w += w * v.w;
        if (l16 == 0) wout[slot] = w;                     // normalized weights
    }

    // Reduce acc across the 16 slot-groups (per dim-lane l16)
    __shared__ float4 sh[256];
    sh[tid] = acc;
    __syncthreads();
    #pragma unroll
    for (int stride = 128; stride >= 16; stride >>= 1) {
        if (tid < stride) {
            float4 o = sh[tid + stride];
            sh[tid].x += o.x; sh[tid].y += o.y;
            sh[tid].z += o.z; sh[tid].w += o.w;
        }
        __syncthreads();
    }
    if (tid < 16) {
        float4 r = sh[tid];
        float* dst = out + OUT_OUTPUTS_OFF + u * D + tid * 4;
        atomicAdd(dst + 0, r.x);
        atomicAdd(dst + 1, r.y);
        atomicAdd(dst + 2, r.z);
        atomicAdd(dst + 3, r.w);
    }
}

// ---------------------------------------------------------------------------
extern "C" void kernel_launch(void* const* d_in, const int* in_sizes, int n_in,
                              void* d_out, int out_size) {
    const float* attention   = (const float*)d_in[0];  // [U, D]
    const float* attentions  = (const float*)d_in[1];  // [U, M, D]
    const float* memories    = (const float*)d_in[2];  // [U, M, D]
    const float* tmpr        = (const float*)d_in[3];  // [U, 1]
    const int*   mask        = (const int*)d_in[4];    // [U, M] bool as int32

    float* out = (float*)d_out;

    score_kernel<<<U * (M / 16), 256>>>(attention, attentions, tmpr, mask);
    sum_kernel<<<U, 256>>>(out);
    output_kernel<<<U * (M / 128), 256>>>(memories, out);
}

// round 4
// speedup vs baseline: 1.4035x; 1.1177x over previous
#include <cuda_runtime.h>
#include <cuda_bf16.h>

// Problem constants
#define U 64
#define M 8192
#define D 64
#define NEG_INF (-1e9f)

// d_out layout (tuple flatten order): outputs[U*D] | weights[U*M] | memories[U*M*D]
#define OUT_OUTPUTS_OFF 0
#define OUT_WEIGHTS_OFF (U * D)
#define OUT_MEMCOPY_OFF (U * D + U * M)

// Scratch (no cudaMalloc allowed)
__device__ float g_exp[U * M];   // exp(masked score / tmpr), pre-normalization
__device__ float g_sum[U];       // per-unit sum of exps

// ---------------------------------------------------------------------------
// Kernel A: scores -> exp -> scratch.  Pure streaming, MLP=8.
// Block = 256 threads covers 128 consecutive slots of one unit.
// 16 lanes per slot (float4 each); each thread handles 8 slots spaced 16
// apart, issuing all 8 loads up front for memory-level parallelism.
// Grid = U * (M/128) = 4096 blocks.
// ---------------------------------------------------------------------------
__global__ __launch_bounds__(256) void score_kernel(
    const float* __restrict__ attention,       // [U, D]
    const float* __restrict__ attentions,      // [U, M, D]
    const float* __restrict__ tmpr,            // [U, 1]
    const int* __restrict__ mask)              // [U, M] (bool stored as int32)
{
    const int b = blockIdx.x;
    const int u = b >> 6;                 // / (M/128 = 64)
    const int mbase = (b & 63) << 7;      // *128

    const int tid  = threadIdx.x;
    const int lane = tid & 31;
    const int warp = tid >> 5;
    const int grp  = lane >> 4;           // 0 or 1: which slot of the pair
    const int l16  = lane & 15;           // float4 index within the 64-d row

    const int s0 = mbase + warp * 2 + grp;   // slots: s0 + 16*i, i=0..7

    const float4 a4 = *reinterpret_cast<const float4*>(attention + u * D + l16 * 4);
    const float4* __restrict__ av =
        reinterpret_cast<const float4*>(attentions) + ((size_t)u * M) * (D / 4) + l16;

    // 8 independent loads in flight
    float4 v[8];
    #pragma unroll
    for (int i = 0; i < 8; i++)
        v[i] = __ldcs(av + (size_t)(s0 + i * 16) * (D / 4));

    float p[8];
    #pragma unroll
    for (int i = 0; i < 8; i++)
        p[i] = a4.x * v[i].x + a4.y * v[i].y + a4.z * v[i].z + a4.w * v[i].w;

    // 8 interleaved 16-lane reductions
    #pragma unroll
    for (int off = 8; off >= 1; off >>= 1) {
        #pragma unroll
        for (int i = 0; i < 8; i++)
            p[i] += __shfl_down_sync(0xffffffffu, p[i], off, 16);
    }

    if (l16 == 0) {
        const float rt = 1.0f / tmpr[u];
        #pragma unroll
        for (int i = 0; i < 8; i++) {
            const int slot = s0 + i * 16;
            float s = mask[u * M + slot] ? NEG_INF : p[i];
            g_exp[u * M + slot] = __expf(s * rt);  // masked -> exactly 0
        }
    }
}

// ---------------------------------------------------------------------------
// Kernel B: per-unit sum of exps (g_exp is L2-resident) + zero the outputs
// region of d_out (it is poisoned before each timed replay).
// Grid = U blocks, 256 threads.
// ---------------------------------------------------------------------------
__global__ __launch_bounds__(256) void sum_kernel(float* __restrict__ out) {
    const int u = blockIdx.x;
    const int tid = threadIdx.x;

    float s = 0.0f;
    const float4* ev = reinterpret_cast<const float4*>(g_exp + u * M);
    #pragma unroll
    for (int i = 0; i < M / 4 / 256; i++) {     // 8 iterations
        float4 e = ev[i * 256 + tid];
        s += (e.x + e.y) + (e.z + e.w);
    }

    __shared__ float sh[256];
    sh[tid] = s;
    __syncthreads();
    #pragma unroll
    for (int stride = 128; stride >= 32; stride >>= 1) {
        if (tid < stride) sh[tid] += sh[tid + stride];
        __syncthreads();
    }
    if (tid < 32) {
        float v = sh[tid];
        #pragma unroll
        for (int off = 16; off >= 1; off >>= 1)
            v += __shfl_down_sync(0xffffffffu, v, off);
        if (tid == 0) g_sum[u] = v;
    }

    if (tid < D) out[OUT_OUTPUTS_OFF + u * D + tid] = 0.0f;
}

// ---------------------------------------------------------------------------
// Kernel C: normalize -> weights out; stream memories once -> weighted sum
// (shared reduce + atomics into outputs) AND verbatim copy to d_out.
// Block = 256 threads covers 128 consecutive slots of one unit.
// Grid = U * (M/128) = 4096 blocks.
// ---------------------------------------------------------------------------
__global__ __launch_bounds__(256) void output_kernel(
    const float* __restrict__ memories,   // [U, M, D]
    float* __restrict__ out)
{
    const int b = blockIdx.x;
    const int u = b >> 6;                 // / (M/128 = 64)
    const int mbase = (b & 63) << 7;      // *128

    const int tid = threadIdx.x;
    const int g   = tid >> 4;             // slot-group 0..15
    const int l16 = tid & 15;             // float4 index within 64-d row

    const float inv = 1.0f / g_sum[u];

    const float4* __restrict__ memv =
        reinterpret_cast<const float4*>(memories) + ((size_t)u * M) * (D / 4);
    float4* __restrict__ copyv =
        reinterpret_cast<float4*>(out + OUT_MEMCOPY_OFF) + ((size_t)u * M) * (D / 4);
    float* __restrict__ wout = out + OUT_WEIGHTS_OFF + u * M;

    float4 acc = make_float4(0.f, 0.f, 0.f, 0.f);

    #pragma unroll
    for (int i = 0; i < 8; i++) {
        const int slot = mbase + i * 16 + g;
        const float w = g_exp[u * M + slot] * inv;
        const float4 v = __ldcs(memv + (size_t)slot * (D / 4) + l16);
        __stcs(copyv + (size_t)slot * (D / 4) + l16, v);  // verbatim copy
        acc.x += w * v.x; acc.y += w * v.y;
        acc.z += w * v.z; acc.w += w * v.w;
        if (l16 == 0) wout[slot] = w;                     // normalized weights
    }

    // Reduce acc across the 16 slot-groups (per dim-lane l16)
    __shared__ float4 sh[256];
    sh[tid] = acc;
    __syncthreads();
    #pragma unroll
    for (int stride = 128; stride >= 16; stride >>= 1) {
        if (tid < stride) {
            float4 o = sh[tid + stride];
            sh[tid].x += o.x; sh[tid].y += o.y;
            sh[tid].z += o.z; sh[tid].w += o.w;
        }
        __syncthreads();
    }
    if (tid < 16) {
        float4 r = sh[tid];
        float* dst = out + OUT_OUTPUTS_OFF + u * D + tid * 4;
        atomicAdd(dst + 0, r.x);
        atomicAdd(dst + 1, r.y);
        atomicAdd(dst + 2, r.z);
        atomicAdd(dst + 3, r.w);
    }
}

// ---------------------------------------------------------------------------
extern "C" void kernel_launch(void* const* d_in, const int* in_sizes, int n_in,
                              void* d_out, int out_size) {
    const float* attention   = (const float*)d_in[0];  // [U, D]
    const float* attentions  = (const float*)d_in[1];  // [U, M, D]
    const float* memories    = (const float*)d_in[2];  // [U, M, D]
    const float* tmpr        = (const float*)d_in[3];  // [U, 1]
    const int*   mask        = (const int*)d_in[4];    // [U, M] bool as int32

    float* out = (float*)d_out;

    score_kernel<<<U * (M / 128), 256>>>(attention, attentions, tmpr, mask);
    sum_kernel<<<U, 256>>>(out);
    output_kernel<<<U * (M / 128), 256>>>(memories, out);
}

// round 9
// speedup vs baseline: 1.4889x; 1.0608x over previous
#include <cuda_runtime.h>
#include <cuda_bf16.h>

// Problem constants
#define U 64
#define M 8192
#define D 64
#define NEG_INF (-1e9f)

// d_out layout (tuple flatten order): outputs[U*D] | weights[U*M] | memories[U*M*D]
#define OUT_OUTPUTS_OFF 0
#define OUT_WEIGHTS_OFF (U * D)
#define OUT_MEMCOPY_OFF (U * D + U * M)

// Scratch (no cudaMalloc allowed)
__device__ float g_exp[U * M];   // exp(masked score / tmpr), pre-normalization
__device__ float g_sum[U];       // per-unit sum of exps

// Volatile vector load: forces issue-order (front-batched MLP), streaming hint.
__device__ __forceinline__ float4 ldcs_v4(const float4* p) {
    float4 r;
    asm volatile("ld.global.cs.v4.f32 {%0,%1,%2,%3}, [%4];"
                 : "=f"(r.x), "=f"(r.y), "=f"(r.z), "=f"(r.w) : "l"(p));
    return r;
}

// ---------------------------------------------------------------------------
// Kernel A: scores -> exp -> scratch.  Pure streaming, forced MLP=8.
// Block = 256 threads covers 128 consecutive slots of one unit.
// 16 lanes per slot (float4 each); each thread handles 8 slots spaced 16
// apart.  All 8 row loads + 8 mask loads + tmpr issued up front.
// Grid = U * (M/128) = 4096 blocks.
// ---------------------------------------------------------------------------
__global__ __launch_bounds__(256) void score_kernel(
    const float* __restrict__ attention,       // [U, D]
    const float* __restrict__ attentions,      // [U, M, D]
    const float* __restrict__ tmpr,            // [U, 1]
    const int* __restrict__ mask)              // [U, M] (bool stored as int32)
{
    const int b = blockIdx.x;
    const int u = b >> 6;                 // / (M/128 = 64)
    const int mbase = (b & 63) << 7;      // *128

    const int tid  = threadIdx.x;
    const int lane = tid & 31;
    const int warp = tid >> 5;
    const int grp  = lane >> 4;           // 0 or 1: which slot of the pair
    const int l16  = lane & 15;           // float4 index within the 64-d row

    const int s0 = mbase + warp * 2 + grp;   // slots: s0 + 16*i, i=0..7

    const float4* __restrict__ av =
        reinterpret_cast<const float4*>(attentions) + ((size_t)u * M) * (D / 4) + l16;

    // All long-latency loads issued first, in order.
    float4 v[8];
    #pragma unroll
    for (int i = 0; i < 8; i++)
        v[i] = ldcs_v4(av + (size_t)(s0 + i * 16) * (D / 4));

    int m[8];
    #pragma unroll
    for (int i = 0; i < 8; i++)
        m[i] = __ldg(mask + u * M + s0 + i * 16);   // same addr across 16-lane grp

    const float rt = 1.0f / __ldg(tmpr + u);
    const float4 a4 = *reinterpret_cast<const float4*>(attention + u * D + l16 * 4);

    float p[8];
    #pragma unroll
    for (int i = 0; i < 8; i++)
        p[i] = a4.x * v[i].x + a4.y * v[i].y + a4.z * v[i].z + a4.w * v[i].w;

    // 8 interleaved 16-lane reductions
    #pragma unroll
    for (int off = 8; off >= 1; off >>= 1) {
        #pragma unroll
        for (int i = 0; i < 8; i++)
            p[i] += __shfl_down_sync(0xffffffffu, p[i], off, 16);
    }

    if (l16 == 0) {
        #pragma unroll
        for (int i = 0; i < 8; i++) {
            const float s = m[i] ? NEG_INF : p[i];
            g_exp[u * M + s0 + i * 16] = __expf(s * rt);  // masked -> exactly 0
        }
    }
}

// ---------------------------------------------------------------------------
// Kernel B: per-unit sum of exps (g_exp is L2-resident) + zero the outputs
// region of d_out (it is poisoned before each timed replay).
// Grid = U blocks, 256 threads.
// ---------------------------------------------------------------------------
__global__ __launch_bounds__(256) void sum_kernel(float* __restrict__ out) {
    const int u = blockIdx.x;
    const int tid = threadIdx.x;

    float s = 0.0f;
    const float4* ev = reinterpret_cast<const float4*>(g_exp + u * M);
    #pragma unroll
    for (int i = 0; i < M / 4 / 256; i++) {     // 8 iterations
        float4 e = ev[i * 256 + tid];
        s += (e.x + e.y) + (e.z + e.w);
    }

    __shared__ float sh[256];
    sh[tid] = s;
    __syncthreads();
    #pragma unroll
    for (int stride = 128; stride >= 32; stride >>= 1) {
        if (tid < stride) sh[tid] += sh[tid + stride];
        __syncthreads();
    }
    if (tid < 32) {
        float v = sh[tid];
        #pragma unroll
        for (int off = 16; off >= 1; off >>= 1)
            v += __shfl_down_sync(0xffffffffu, v, off);
        if (tid == 0) g_sum[u] = v;
    }

    if (tid < D) out[OUT_OUTPUTS_OFF + u * D + tid] = 0.0f;
}

// ---------------------------------------------------------------------------
// Kernel C: normalize -> weights out; stream memories once -> weighted sum
// (shared reduce + atomics into outputs) AND verbatim copy to d_out.
// Forced MLP: 8 exp loads + 8 float4 loads all issued up front.
// Block = 256 threads covers 128 consecutive slots of one unit.
// Grid = U * (M/128) = 4096 blocks.
// ---------------------------------------------------------------------------
__global__ __launch_bounds__(256) void output_kernel(
    const float* __restrict__ memories,   // [U, M, D]
    float* __restrict__ out)
{
    const int b = blockIdx.x;
    const int u = b >> 6;                 // / (M/128 = 64)
    const int mbase = (b & 63) << 7;      // *128

    const int tid = threadIdx.x;
    const int g   = tid >> 4;             // slot-group 0..15
    const int l16 = tid & 15;             // float4 index within 64-d row

    const float4* __restrict__ memv =
        reinterpret_cast<const float4*>(memories) + ((size_t)u * M) * (D / 4);
    float4* __restrict__ copyv =
        reinterpret_cast<float4*>(out + OUT_MEMCOPY_OFF) + ((size_t)u * M) * (D / 4);
    float* __restrict__ wout = out + OUT_WEIGHTS_OFF + u * M;

    // Front-issue all long-latency loads.
    float4 v[8];
    #pragma unroll
    for (int i = 0; i < 8; i++)
        v[i] = ldcs_v4(memv + (size_t)(mbase + i * 16 + g) * (D / 4) + l16);

    float e[8];
    #pragma unroll
    for (int i = 0; i < 8; i++)
        e[i] = __ldg(g_exp + u * M + mbase + i * 16 + g);  // broadcast in grp

    const float inv = 1.0f / g_sum[u];

    float4 acc = make_float4(0.f, 0.f, 0.f, 0.f);
    #pragma unroll
    for (int i = 0; i < 8; i++) {
        const int slot = mbase + i * 16 + g;
        const float w = e[i] * inv;
        __stcs(copyv + (size_t)slot * (D / 4) + l16, v[i]);  // verbatim copy
        acc.x += w * v[i].x; acc.y += w * v[i].y;
        acc.z += w * v[i].z; acc.w += w * v[i].w;
        if (l16 == 0) wout[slot] = w;                        // normalized weights
    }

    // Reduce acc across the 16 slot-groups (per dim-lane l16)
    __shared__ float4 sh[256];
    sh[tid] = acc;
    __syncthreads();
    #pragma unroll
    for (int stride = 128; stride >= 16; stride >>= 1) {
        if (tid < stride) {
            float4 o = sh[tid + stride];
            sh[tid].x += o.x; sh[tid].y += o.y;
            sh[tid].z += o.z; sh[tid].w += o.w;
        }
        __syncthreads();
    }
    if (tid < 16) {
        float4 r = sh[tid];
        float* dst = out + OUT_OUTPUTS_OFF + u * D + tid * 4;
        atomicAdd(dst + 0, r.x);
        atomicAdd(dst + 1, r.y);
        atomicAdd(dst + 2, r.z);
        atomicAdd(dst + 3, r.w);
    }
}

// ---------------------------------------------------------------------------
extern "C" void kernel_launch(void* const* d_in, const int* in_sizes, int n_in,
                              void* d_out, int out_size) {
    const float* attention   = (const float*)d_in[0];  // [U, D]
    const float* attentions  = (const float*)d_in[1];  // [U, M, D]
    const float* memories    = (const float*)d_in[2];  // [U, M, D]
    const float* tmpr        = (const float*)d_in[3];  // [U, 1]
    const int*   mask        = (const int*)d_in[4];    // [U, M] bool as int32

    float* out = (float*)d_out;

    score_kernel<<<U * (M / 128), 256>>>(attention, attentions, tmpr, mask);
    sum_kernel<<<U, 256>>>(out);
    output_kernel<<<U * (M / 128), 256>>>(memories, out);
}

// round 14
// speedup vs baseline: 1.5414x; 1.0352x over previous
#include <cuda_runtime.h>
#include <cuda_bf16.h>

// Problem constants
#define U 64
#define M 8192
#define D 64
#define NEG_INF (-1e9f)

// d_out layout (tuple flatten order): outputs[U*D] | weights[U*M] | memories[U*M*D]
#define OUT_OUTPUTS_OFF 0
#define OUT_WEIGHTS_OFF (U * D)
#define OUT_MEMCOPY_OFF (U * D + U * M)

// Scratch (no cudaMalloc allowed)
__device__ float g_exp[U * M];        // exp(masked score / tmpr), pre-normalization
__device__ float g_partial[U * 64];   // per-block partial sums (block-major = unit-major)

// Single asm block: 8x LDG.128 with immediate offsets (stride 4096B = 16 slots).
// ptxas cannot split one asm statement -> all 32 result regs live at once -> MLP=8.
__device__ __forceinline__ void ld8_v4_s4096(const float4* base, float4 v[8]) {
    asm volatile(
        "ld.global.cs.v4.f32 {%0,%1,%2,%3}, [%32];\n\t"
        "ld.global.cs.v4.f32 {%4,%5,%6,%7}, [%32+4096];\n\t"
        "ld.global.cs.v4.f32 {%8,%9,%10,%11}, [%32+8192];\n\t"
        "ld.global.cs.v4.f32 {%12,%13,%14,%15}, [%32+12288];\n\t"
        "ld.global.cs.v4.f32 {%16,%17,%18,%19}, [%32+16384];\n\t"
        "ld.global.cs.v4.f32 {%20,%21,%22,%23}, [%32+20480];\n\t"
        "ld.global.cs.v4.f32 {%24,%25,%26,%27}, [%32+24576];\n\t"
        "ld.global.cs.v4.f32 {%28,%29,%30,%31}, [%32+28672];\n\t"
        : "=f"(v[0].x), "=f"(v[0].y), "=f"(v[0].z), "=f"(v[0].w),
          "=f"(v[1].x), "=f"(v[1].y), "=f"(v[1].z), "=f"(v[1].w),
          "=f"(v[2].x), "=f"(v[2].y), "=f"(v[2].z), "=f"(v[2].w),
          "=f"(v[3].x), "=f"(v[3].y), "=f"(v[3].z), "=f"(v[3].w),
          "=f"(v[4].x), "=f"(v[4].y), "=f"(v[4].z), "=f"(v[4].w),
          "=f"(v[5].x), "=f"(v[5].y), "=f"(v[5].z), "=f"(v[5].w),
          "=f"(v[6].x), "=f"(v[6].y), "=f"(v[6].z), "=f"(v[6].w),
          "=f"(v[7].x), "=f"(v[7].y), "=f"(v[7].z), "=f"(v[7].w)
        : "l"(base));
}

// ---------------------------------------------------------------------------
// Kernel A: scores -> exp -> g_exp, per-block sum -> g_partial.
// Block = 256 threads covers 128 consecutive slots of one unit; 16 lanes per
// slot (float4 each); each thread handles 8 slots spaced 16 apart, all loads
// issued as one asm block (MLP=8).  Blocks b<16 also zero the outputs region.
// Grid = U * (M/128) = 4096 blocks.
// ---------------------------------------------------------------------------
__global__ __launch_bounds__(256) void score_kernel(
    const float* __restrict__ attention,       // [U, D]
    const float* __restrict__ attentions,      // [U, M, D]
    const float* __restrict__ tmpr,            // [U, 1]
    const int* __restrict__ mask,              // [U, M] (bool stored as int32)
    float* __restrict__ out)
{
    const int b = blockIdx.x;
    const int u = b >> 6;                 // / (M/128 = 64)
    const int mbase = (b & 63) << 7;      // *128

    const int tid  = threadIdx.x;
    const int lane = tid & 31;
    const int warp = tid >> 5;
    const int grp  = lane >> 4;           // 0 or 1: which slot of the pair
    const int l16  = lane & 15;           // float4 index within the 64-d row

    const int s0 = mbase + warp * 2 + grp;   // slots: s0 + 16*i, i=0..7

    const float4* __restrict__ av =
        reinterpret_cast<const float4*>(attentions) + ((size_t)u * M + s0) * (D / 4) + l16;

    float4 v[8];
    ld8_v4_s4096(av, v);                      // 8 LDG.128 in flight

    // Zero the outputs region of d_out (poisoned each replay): 16 blocks x 256.
    if (b < 16) out[OUT_OUTPUTS_OFF + b * 256 + tid] = 0.0f;

    int m[8];
    #pragma unroll
    for (int i = 0; i < 8; i++)
        m[i] = __ldg(mask + u * M + s0 + i * 16);   // broadcast within group

    const float rt = 1.0f / __ldg(tmpr + u);
    const float4 a4 = *reinterpret_cast<const float4*>(attention + u * D + l16 * 4);

    float p[8];
    #pragma unroll
    for (int i = 0; i < 8; i++)
        p[i] = a4.x * v[i].x + a4.y * v[i].y + a4.z * v[i].z + a4.w * v[i].w;

    #pragma unroll
    for (int off = 8; off >= 1; off >>= 1) {
        #pragma unroll
        for (int i = 0; i < 8; i++)
            p[i] += __shfl_down_sync(0xffffffffu, p[i], off, 16);
    }

    // Leaders (l16==0, lanes 0 and 16 of each warp) hold 8 exps each.
    float le = 0.0f;
    if (l16 == 0) {
        #pragma unroll
        for (int i = 0; i < 8; i++) {
            const float s = m[i] ? NEG_INF : p[i];
            const float e = __expf(s * rt);       // masked -> exactly 0
            g_exp[u * M + s0 + i * 16] = e;
            le += e;
        }
    }
    // Warp partial: lane0 += lane16's value.
    le += __shfl_down_sync(0xffffffffu, le, 16);

    __shared__ float shp[8];
    if (lane == 0) shp[warp] = le;
    __syncthreads();
    if (tid == 0) {
        float s = 0.0f;
        #pragma unroll
        for (int w = 0; w < 8; w++) s += shp[w];
        g_partial[b] = s;                         // b is already unit-major
    }
}

// ---------------------------------------------------------------------------
// Kernel B: normalize -> weights out; stream memories once -> weighted sum
// (shared reduce + atomics into outputs) AND verbatim copy to d_out.
// Per-unit softmax denominator assembled from 64 L2-resident partials while
// the 8 big loads (one asm block, MLP=8) are in flight.
// Block = 256 threads covers 128 consecutive slots of one unit.
// Grid = U * (M/128) = 4096 blocks.
// ---------------------------------------------------------------------------
__global__ __launch_bounds__(256) void output_kernel(
    const float* __restrict__ memories,   // [U, M, D]
    float* __restrict__ out)
{
    const int b = blockIdx.x;
    const int u = b >> 6;                 // / (M/128 = 64)
    const int mbase = (b & 63) << 7;      // *128

    const int tid  = threadIdx.x;
    const int lane = tid & 31;
    const int g    = tid >> 4;            // slot-group 0..15
    const int l16  = tid & 15;            // float4 index within 64-d row

    const float4* __restrict__ memv =
        reinterpret_cast<const float4*>(memories) + ((size_t)u * M) * (D / 4);
    float4* __restrict__ copyv =
        reinterpret_cast<float4*>(out + OUT_MEMCOPY_OFF) + ((size_t)u * M) * (D / 4);
    float* __restrict__ wout = out + OUT_WEIGHTS_OFF + u * M;

    // Front-issue the 8 big loads (slots mbase + g + 16*i, stride 4096B).
    float4 v[8];
    ld8_v4_s4096(memv + (size_t)(mbase + g) * (D / 4) + l16, v);

    float e[8];
    #pragma unroll
    for (int i = 0; i < 8; i++)
        e[i] = __ldg(g_exp + u * M + mbase + i * 16 + g);  // broadcast in grp

    // Warp 0 reduces the unit's 64 partial sums (L2-hot) -> inv denominator.
    __shared__ float sh_inv;
    if (tid < 32) {
        float s = g_partial[(u << 6) + lane] + g_partial[(u << 6) + 32 + lane];
        #pragma unroll
        for (int off = 16; off >= 1; off >>= 1)
            s += __shfl_down_sync(0xffffffffu, s, off);
        if (tid == 0) sh_inv = 1.0f / s;
    }
    __syncthreads();
    const float inv = sh_inv;

    float4 acc = make_float4(0.f, 0.f, 0.f, 0.f);
    #pragma unroll
    for (int i = 0; i < 8; i++) {
        const int slot = mbase + i * 16 + g;
        const float w = e[i] * inv;
        __stcs(copyv + (size_t)slot * (D / 4) + l16, v[i]);  // verbatim copy
        acc.x += w * v[i].x; acc.y += w * v[i].y;
        acc.z += w * v[i].z; acc.w += w * v[i].w;
        if (l16 == 0) wout[slot] = w;                        // normalized weights
    }

    // Reduce acc across the 16 slot-groups (per dim-lane l16)
    __shared__ float4 sh[256];
    sh[tid] = acc;
    __syncthreads();
    #pragma unroll
    for (int stride = 128; stride >= 16; stride >>= 1) {
        if (tid < stride) {
            float4 o = sh[tid + stride];
            sh[tid].x += o.x; sh[tid].y += o.y;
            sh[tid].z += o.z; sh[tid].w += o.w;
        }
        __syncthreads();
    }
    if (tid < 16) {
        float4 r = sh[tid];
        float* dst = out + OUT_OUTPUTS_OFF + u * D + tid * 4;
        atomicAdd(dst + 0, r.x);
        atomicAdd(dst + 1, r.y);
        atomicAdd(dst + 2, r.z);
        atomicAdd(dst + 3, r.w);
    }
}

// ---------------------------------------------------------------------------
extern "C" void kernel_launch(void* const* d_in, const int* in_sizes, int n_in,
                              void* d_out, int out_size) {
    const float* attention   = (const float*)d_in[0];  // [U, D]
    const float* attentions  = (const float*)d_in[1];  // [U, M, D]
    const float* memories    = (const float*)d_in[2];  // [U, M, D]
    const float* tmpr        = (const float*)d_in[3];  // [U, 1]
    const int*   mask        = (const int*)d_in[4];    // [U, M] bool as int32

    float* out = (float*)d_out;

    score_kernel<<<U * (M / 128), 256>>>(attention, attentions, tmpr, mask, out);
    output_kernel<<<U * (M / 128), 256>>>(memories, out);
}

// round 16
// speedup vs baseline: 1.5845x; 1.0280x over previous
#include <cuda_runtime.h>
#include <cuda_bf16.h>

// Problem constants
#define U 64
#define M 8192
#define D 64
#define NEG_INF (-1e9f)

// d_out layout (tuple flatten order): outputs[U*D] | weights[U*M] | memories[U*M*D]
#define OUT_OUTPUTS_OFF 0
#define OUT_WEIGHTS_OFF (U * D)
#define OUT_MEMCOPY_OFF (U * D + U * M)

// Scratch (no cudaMalloc allowed).  g_outacc starts zero (module init) and is
// re-zeroed by the epilogue after reading -> clean for every graph replay.
__device__ float g_partial[U * 64];   // per-block sums of exp (block-major = unit-major)
__device__ float g_outacc[U * D];     // unnormalized sum of e * mem

// Single asm block: 8x LDG.128, immediate offsets, stride 256B = one 64-float
// slot row.  Loads 8 CONSECUTIVE slot rows for a 16-lane group (lane l16 owns
// bytes [l16*16, l16*16+16) of each row).  One asm statement cannot be split
// by ptxas -> all 32 result registers simultaneously live -> true MLP=8.
__device__ __forceinline__ void ld8_v4_s256(const float4* base, float4 v[8]) {
    asm volatile(
        "ld.global.cs.v4.f32 {%0,%1,%2,%3}, [%32];\n\t"
        "ld.global.cs.v4.f32 {%4,%5,%6,%7}, [%32+256];\n\t"
        "ld.global.cs.v4.f32 {%8,%9,%10,%11}, [%32+512];\n\t"
        "ld.global.cs.v4.f32 {%12,%13,%14,%15}, [%32+768];\n\t"
        "ld.global.cs.v4.f32 {%16,%17,%18,%19}, [%32+1024];\n\t"
        "ld.global.cs.v4.f32 {%20,%21,%22,%23}, [%32+1280];\n\t"
        "ld.global.cs.v4.f32 {%24,%25,%26,%27}, [%32+1536];\n\t"
        "ld.global.cs.v4.f32 {%28,%29,%30,%31}, [%32+1792];\n\t"
        : "=f"(v[0].x), "=f"(v[0].y), "=f"(v[0].z), "=f"(v[0].w),
          "=f"(v[1].x), "=f"(v[1].y), "=f"(v[1].z), "=f"(v[1].w),
          "=f"(v[2].x), "=f"(v[2].y), "=f"(v[2].z), "=f"(v[2].w),
          "=f"(v[3].x), "=f"(v[3].y), "=f"(v[3].z), "=f"(v[3].w),
          "=f"(v[4].x), "=f"(v[4].y), "=f"(v[4].z), "=f"(v[4].w),
          "=f"(v[5].x), "=f"(v[5].y), "=f"(v[5].z), "=f"(v[5].w),
          "=f"(v[6].x), "=f"(v[6].y), "=f"(v[6].z), "=f"(v[6].w),
          "=f"(v[7].x), "=f"(v[7].y), "=f"(v[7].z), "=f"(v[7].w)
        : "l"(base));
}

// ---------------------------------------------------------------------------
// Fused kernel: one pass over attentions + memories for a 128-slot tile.
//  - 16-lane groups own 8 CONSECUTIVE slots (coalesced loads per slot row;
//    leader weight-writes become two STG.128).
//  - e = exp(masked score / tmpr) written UNNORMALIZED to the weights region.
//  - memories copied verbatim; unnormalized e*mem accumulated into g_outacc.
//  - per-block sum of e -> g_partial.
// Grid = U * (M/128) = 4096 blocks, 256 threads.
// ---------------------------------------------------------------------------
__global__ __launch_bounds__(256) void fused_kernel(
    const float* __restrict__ attention,       // [U, D]
    const float* __restrict__ attentions,      // [U, M, D]
    const float* __restrict__ memories,        // [U, M, D]
    const float* __restrict__ tmpr,            // [U, 1]
    const int* __restrict__ mask,              // [U, M] (bool stored as int32)
    float* __restrict__ out)
{
    const int b = blockIdx.x;
    const int u = b >> 6;                 // / (M/128 = 64)
    const int mbase = (b & 63) << 7;      // *128

    const int tid  = threadIdx.x;
    const int lane = tid & 31;
    const int warp = tid >> 5;
    const int grp  = lane >> 4;           // 0 or 1
    const int l16  = lane & 15;           // float4 index within the 64-d row

    const int sbase = mbase + (warp * 2 + grp) * 8;   // 8 consecutive slots

    // Front-issue ALL long-latency loads (16 LDG.128 + mask + scalars).
    const float4* __restrict__ av =
        reinterpret_cast<const float4*>(attentions) + ((size_t)u * M + sbase) * (D / 4) + l16;
    float4 va[8];
    ld8_v4_s256(av, va);

    const float4* __restrict__ mv =
        reinterpret_cast<const float4*>(memories) + ((size_t)u * M + sbase) * (D / 4) + l16;
    float4 vm[8];
    ld8_v4_s256(mv, vm);

    const int4 m0 = __ldg(reinterpret_cast<const int4*>(mask + u * M + sbase));
    const int4 m1 = __ldg(reinterpret_cast<const int4*>(mask + u * M + sbase + 4));

    const float rt = 1.0f / __ldg(tmpr + u);
    const float4 a4 = *reinterpret_cast<const float4*>(attention + u * D + l16 * 4);

    // Scores
    float p[8];
    #pragma unroll
    for (int i = 0; i < 8; i++)
        p[i] = a4.x * va[i].x + a4.y * va[i].y + a4.z * va[i].z + a4.w * va[i].w;

    #pragma unroll
    for (int off = 8; off >= 1; off >>= 1) {
        #pragma unroll
        for (int i = 0; i < 8; i++)
            p[i] += __shfl_down_sync(0xffffffffu, p[i], off, 16);
    }

    // Leaders (l16==0) compute the 8 exps; broadcast to the group.
    float e[8] = {0, 0, 0, 0, 0, 0, 0, 0};
    float le = 0.0f;
    if (l16 == 0) {
        const int mm[8] = {m0.x, m0.y, m0.z, m0.w, m1.x, m1.y, m1.z, m1.w};
        #pragma unroll
        for (int i = 0; i < 8; i++) {
            const float s = mm[i] ? NEG_INF : p[i];
            e[i] = __expf(s * rt);            // masked -> exactly 0
            le += e[i];
        }
        // Unnormalized weights: 8 consecutive floats = two STG.128.
        float* wp = out + OUT_WEIGHTS_OFF + u * M + sbase;
        *reinterpret_cast<float4*>(wp)     = make_float4(e[0], e[1], e[2], e[3]);
        *reinterpret_cast<float4*>(wp + 4) = make_float4(e[4], e[5], e[6], e[7]);
    }
    #pragma unroll
    for (int i = 0; i < 8; i++)
        e[i] = __shfl_sync(0xffffffffu, e[i], 0, 16);

    // Copy memories + accumulate unnormalized weighted sum.
    float4* __restrict__ copyv =
        reinterpret_cast<float4*>(out + OUT_MEMCOPY_OFF) + ((size_t)u * M + sbase) * (D / 4) + l16;
    float4 acc = make_float4(0.f, 0.f, 0.f, 0.f);
    #pragma unroll
    for (int i = 0; i < 8; i++) {
        __stcs(copyv + (size_t)i * (D / 4), vm[i]);
        acc.x += e[i] * vm[i].x; acc.y += e[i] * vm[i].y;
        acc.z += e[i] * vm[i].z; acc.w += e[i] * vm[i].w;
    }

    // Per-block exp-sum -> g_partial (plain store; b is unit-major).
    le += __shfl_down_sync(0xffffffffu, le, 16);
    __shared__ float shp[8];
    if (lane == 0) shp[warp] = le;

    // Reduce acc across the 16 groups (per dim-lane l16).
    __shared__ float4 sh[256];
    const int gidx = warp * 2 + grp;           // group 0..15
    sh[gidx * 16 + l16] = acc;
    __syncthreads();
    if (tid == 0) {
        float s = 0.0f;
        #pragma unroll
        for (int w = 0; w < 8; w++) s += shp[w];
        g_partial[b] = s;
    }
    #pragma unroll
    for (int stride = 128; stride >= 16; stride >>= 1) {
        if (tid < stride) {
            float4 o = sh[tid + stride];
            sh[tid].x += o.x; sh[tid].y += o.y;
            sh[tid].z += o.z; sh[tid].w += o.w;
        }
        __syncthreads();
    }
    if (tid < 16) {
        float4 r = sh[tid];
        float* dst = g_outacc + u * D + tid * 4;
        atomicAdd(dst + 0, r.x);
        atomicAdd(dst + 1, r.y);
        atomicAdd(dst + 2, r.z);
        atomicAdd(dst + 3, r.w);
    }
}

// ---------------------------------------------------------------------------
// Epilogue: per unit, reduce 64 partials -> inv denominator; scale the
// weights region in-place (L2-hot, 2 MB total); write outputs = acc * inv;
// re-zero g_outacc for the next replay.  Grid = U blocks, 256 threads.
// ---------------------------------------------------------------------------
__global__ __launch_bounds__(256) void epilogue_kernel(float* __restrict__ out) {
    const int u = blockIdx.x;
    const int tid = threadIdx.x;
    const int lane = tid & 31;

    __shared__ float sh_inv;
    if (tid < 32) {
        float s = g_partial[(u << 6) + lane] + g_partial[(u << 6) + 32 + lane];
        #pragma unroll
        for (int off = 16; off >= 1; off >>= 1)
            s += __shfl_down_sync(0xffffffffu, s, off);
        if (tid == 0) sh_inv = 1.0f / s;
    }
    __syncthreads();
    const float inv = sh_inv;

    // Normalize weights in place: 8192 floats = 2048 float4 per unit.
    float4* w = reinterpret_cast<float4*>(out + OUT_WEIGHTS_OFF + u * M);
    #pragma unroll
    for (int i = 0; i < 8; i++) {
        float4 v = w[i * 256 + tid];
        v.x *= inv; v.y *= inv; v.z *= inv; v.w *= inv;
        w[i * 256 + tid] = v;
    }

    // Outputs + reset accumulator for the next graph replay.
    if (tid < D) {
        out[OUT_OUTPUTS_OFF + u * D + tid] = g_outacc[u * D + tid] * inv;
        g_outacc[u * D + tid] = 0.0f;
    }
}

// ---------------------------------------------------------------------------
extern "C" void kernel_launch(void* const* d_in, const int* in_sizes, int n_in,
                              void* d_out, int out_size) {
    const float* attention   = (const float*)d_in[0];  // [U, D]
    const float* attentions  = (const float*)d_in[1];  // [U, M, D]
    const float* memories    = (const float*)d_in[2];  // [U, M, D]
    const float* tmpr        = (const float*)d_in[3];  // [U, 1]
    const int*   mask        = (const int*)d_in[4];    // [U, M] bool as int32

    float* out = (float*)d_out;

    fused_kernel<<<U * (M / 128), 256>>>(attention, attentions, memories, tmpr, mask, out);
    epilogue_kernel<<<U, 256>>>(out);
}